// round 1
// baseline (speedup 1.0000x reference)
#include <cuda_runtime.h>
#include <math.h>
#include <stdint.h>

// Problem constants (fixed by setup_inputs)
#define BATCH   2
#define IMG     224            // H = W_img = 224, divisible by WS -> no padding
#define TOKENS  (BATCH*IMG*IMG)   // 100352
#define DIM     768
#define NH      12
#define HD      64
#define WS      7
#define L       (WS*WS)        // 49
#define NWIN    (BATCH*(IMG/WS)*(IMG/WS))  // 2048
#define SHIFT   3              // WS/2, shift=1 in setup

// Scratch (device globals: allocation is forbidden in kernel_launch)
__device__ float g_qkv[(size_t)TOKENS * 3 * DIM];   // 100352 x 2304
__device__ float g_att[(size_t)TOKENS * DIM];       // 100352 x 768
__device__ float g_sin[L * 32];
__device__ float g_cos[L * 32];

// ---------------------------------------------------------------------------
// RoPE tables: ang[tok, 0:16] = ty * inv[f], ang[tok, 16:32] = tx * inv[f]
// inv[f] = 100^(-f/16)
// ---------------------------------------------------------------------------
__global__ void rope_init_kernel() {
    for (int i = threadIdx.x; i < L * 32; i += blockDim.x) {
        int tok = i >> 5, d = i & 31;
        int ty = tok / WS, tx = tok - ty * WS;
        int f = d & 15;
        float inv = powf(100.0f, -((float)f) / 16.0f);
        float ang = ((d < 16) ? (float)ty : (float)tx) * inv;
        g_sin[i] = sinf(ang);
        g_cos[i] = cosf(ang);
    }
}

// ---------------------------------------------------------------------------
// SGEMM:  C[M,N] = A[M,K] @ W[N,K]^T    (both operands K-contiguous)
// 128x128 block tile, BK=8, 256 threads, 8x8 per-thread microtile,
// float4 global loads with register prefetch.
// Requires M%128==0, N%128==0, K%8==0 (true for all calls here).
// ---------------------------------------------------------------------------
__global__ __launch_bounds__(256) void sgemm_tn_kernel(
    const float* __restrict__ A, const float* __restrict__ W,
    float* __restrict__ C, int M, int N, int K)
{
    const int BM = 128, BN = 128, BK = 8;
    __shared__ __align__(16) float As[BK][BM];
    __shared__ __align__(16) float Bs[BK][BN];

    int tid  = threadIdx.x;
    int lrow = tid >> 1;           // 0..127
    int lk4  = (tid & 1) << 2;     // 0 or 4

    const float* Ap = A + (size_t)(blockIdx.y * BM + lrow) * K + lk4;
    const float* Wp = W + (size_t)(blockIdx.x * BN + lrow) * K + lk4;

    int tn = (tid & 15) << 3;      // 0..120
    int tm = (tid >> 4) << 3;      // 0..120

    float acc[8][8];
#pragma unroll
    for (int i = 0; i < 8; ++i)
#pragma unroll
        for (int j = 0; j < 8; ++j) acc[i][j] = 0.0f;

    float4 a4 = *(const float4*)Ap;
    float4 b4 = *(const float4*)Wp;

    for (int k0 = 0; k0 < K; k0 += BK) {
        As[lk4 + 0][lrow] = a4.x; As[lk4 + 1][lrow] = a4.y;
        As[lk4 + 2][lrow] = a4.z; As[lk4 + 3][lrow] = a4.w;
        Bs[lk4 + 0][lrow] = b4.x; Bs[lk4 + 1][lrow] = b4.y;
        Bs[lk4 + 2][lrow] = b4.z; Bs[lk4 + 3][lrow] = b4.w;
        __syncthreads();

        if (k0 + BK < K) {
            a4 = *(const float4*)(Ap + k0 + BK);
            b4 = *(const float4*)(Wp + k0 + BK);
        }

#pragma unroll
        for (int kk = 0; kk < BK; ++kk) {
            float4 ra0 = *(const float4*)&As[kk][tm];
            float4 ra1 = *(const float4*)&As[kk][tm + 4];
            float4 rb0 = *(const float4*)&Bs[kk][tn];
            float4 rb1 = *(const float4*)&Bs[kk][tn + 4];
            float ra[8] = {ra0.x, ra0.y, ra0.z, ra0.w, ra1.x, ra1.y, ra1.z, ra1.w};
            float rb[8] = {rb0.x, rb0.y, rb0.z, rb0.w, rb1.x, rb1.y, rb1.z, rb1.w};
#pragma unroll
            for (int i = 0; i < 8; ++i)
#pragma unroll
                for (int j = 0; j < 8; ++j)
                    acc[i][j] += ra[i] * rb[j];
        }
        __syncthreads();
    }

    float* Cp = C + (size_t)(blockIdx.y * BM + tm) * N + blockIdx.x * BN + tn;
#pragma unroll
    for (int i = 0; i < 8; ++i) {
        *(float4*)(Cp + (size_t)i * N)     = make_float4(acc[i][0], acc[i][1], acc[i][2], acc[i][3]);
        *(float4*)(Cp + (size_t)i * N + 4) = make_float4(acc[i][4], acc[i][5], acc[i][6], acc[i][7]);
    }
}

// ---------------------------------------------------------------------------
// Window attention: one block per (head, window). 64 threads.
// Warp0 loads+RoPEs Q, warp1 loads+RoPEs K and computes k L2-scales via
// warp reduction. q-norm is folded into the logit scale, so q/k never need
// normalized rewrites. Scores/weights live in shared; q-row, out-row in regs.
// Broadcast shared reads keep LDS traffic ~free.
// ---------------------------------------------------------------------------
__global__ __launch_bounds__(64) void window_attn_kernel(
    const float* __restrict__ qkv, float* __restrict__ outp)
{
    __shared__ __align__(16) float Qs[L * 68];   // padded stride to dodge bank conflicts
    __shared__ __align__(16) float Ks[L * 64];
    __shared__ __align__(16) float Vs[L * 64];
    __shared__ float S[L * L];
    __shared__ float kscale[L];
    __shared__ int   grows[L];

    const int h   = blockIdx.x;      // head 0..11
    const int w   = blockIdx.y;      // window 0..2047
    const int tid = threadIdx.x;
    const int b   = w >> 10;         // 1024 windows per batch
    const int rem = w & 1023;
    const int wh  = rem >> 5, ww = rem & 31;

    // token -> original-image row mapping (roll by +3 with wraparound)
    if (tid < L) {
        int ty = tid / WS, tx = tid - ty * WS;
        int y = wh * WS + ty + SHIFT; if (y >= IMG) y -= IMG;
        int x = ww * WS + tx + SHIFT; if (x >= IMG) x -= IMG;
        grows[tid] = b * (IMG * IMG) + y * IMG + x;
    }
    __syncthreads();

    const int lane = tid & 31;
    const int warp = tid >> 5;

    // Load + RoPE q (warp0) and k (warp1); k-scale via warp reduction.
    for (int t = 0; t < L; ++t) {
        size_t base = (size_t)grows[t] * (3 * DIM) + h * HD;
        float s = g_sin[t * 32 + lane];
        float c = g_cos[t * 32 + lane];
        if (warp == 0) {
            float t1 = qkv[base + lane];
            float t2 = qkv[base + lane + 32];
            Qs[t * 68 + lane]      = t1 * c - t2 * s;
            Qs[t * 68 + lane + 32] = t1 * s + t2 * c;
        } else {
            float t1 = qkv[base + DIM + lane];
            float t2 = qkv[base + DIM + lane + 32];
            float r1 = t1 * c - t2 * s;
            float r2 = t1 * s + t2 * c;
            Ks[t * 64 + lane]      = r1;
            Ks[t * 64 + lane + 32] = r2;
            float ssq = r1 * r1 + r2 * r2;
#pragma unroll
            for (int off = 16; off; off >>= 1)
                ssq += __shfl_xor_sync(0xffffffffu, ssq, off);
            if (lane == 0) kscale[t] = 1.0f / fmaxf(sqrtf(ssq), 1e-12f);
        }
    }
    // V (raw)
    for (int t = 0; t < L; ++t) {
        size_t base = (size_t)grows[t] * (3 * DIM) + h * HD + 2 * DIM;
        Vs[t * 64 + tid] = qkv[base + tid];
    }
    __syncthreads();

    if (tid < L) {
        const int i = tid;
        float4 qv[16];
#pragma unroll
        for (int d4 = 0; d4 < 16; ++d4)
            qv[d4] = *(const float4*)&Qs[i * 68 + d4 * 4];

        float ssq = 0.0f;
#pragma unroll
        for (int d4 = 0; d4 < 16; ++d4)
            ssq += qv[d4].x * qv[d4].x + qv[d4].y * qv[d4].y
                 + qv[d4].z * qv[d4].z + qv[d4].w * qv[d4].w;
        float qsc = 1.0f / fmaxf(sqrtf(ssq), 1e-12f);

        // Scores: logit = (q . k) * qscale * kscale * (1/tau)
        float mx = -1e30f;
        for (int j = 0; j < L; ++j) {
            float d0 = 0.f, d1 = 0.f, d2 = 0.f, d3 = 0.f;
#pragma unroll
            for (int d4 = 0; d4 < 16; ++d4) {
                float4 k4 = *(const float4*)&Ks[j * 64 + d4 * 4];  // broadcast
                d0 += qv[d4].x * k4.x; d1 += qv[d4].y * k4.y;
                d2 += qv[d4].z * k4.z; d3 += qv[d4].w * k4.w;
            }
            float logit = (d0 + d1 + d2 + d3) * (qsc * kscale[j] * 100.0f);
            S[i * L + j] = logit;
            mx = fmaxf(mx, logit);
        }
        float sum = 0.0f;
        for (int j = 0; j < L; ++j) {
            float e = __expf(S[i * L + j] - mx);
            S[i * L + j] = e;
            sum += e;
        }

        float ov[64];
#pragma unroll
        for (int d = 0; d < 64; ++d) ov[d] = 0.0f;
        for (int j = 0; j < L; ++j) {
            float wgt = S[i * L + j];
#pragma unroll
            for (int d4 = 0; d4 < 16; ++d4) {
                float4 v4 = *(const float4*)&Vs[j * 64 + d4 * 4];  // broadcast
                ov[d4 * 4 + 0] += wgt * v4.x;
                ov[d4 * 4 + 1] += wgt * v4.y;
                ov[d4 * 4 + 2] += wgt * v4.z;
                ov[d4 * 4 + 3] += wgt * v4.w;
            }
        }
        float isum = 1.0f / sum;
#pragma unroll
        for (int d = 0; d < 64; ++d) Qs[i * 68 + d] = ov[d] * isum;  // stage for coalesced store
    }
    __syncthreads();

    for (int t = 0; t < L; ++t)
        outp[(size_t)grows[t] * DIM + h * HD + tid] = Qs[t * 68 + tid];
}

// ---------------------------------------------------------------------------
extern "C" void kernel_launch(void* const* d_in, const int* in_sizes, int n_in,
                              void* d_out, int out_size)
{
    const float* x     = (const float*)d_in[0];
    const float* qkv_w = (const float*)d_in[1];
    const float* projw = (const float*)d_in[2];
    float* out = (float*)d_out;

    float *qkv_ptr, *att_ptr;
    cudaGetSymbolAddress((void**)&qkv_ptr, g_qkv);
    cudaGetSymbolAddress((void**)&att_ptr, g_att);

    rope_init_kernel<<<1, 256>>>();

    // qkv = x @ qkv_w^T   : M=100352, N=2304, K=768
    sgemm_tn_kernel<<<dim3(3 * DIM / 128, TOKENS / 128), 256>>>(
        x, qkv_w, qkv_ptr, TOKENS, 3 * DIM, DIM);

    // windowed attention (gather/scatter does roll+window permutation)
    window_attn_kernel<<<dim3(NH, NWIN), 64>>>(qkv_ptr, att_ptr);

    // out = att @ proj_w^T : M=100352, N=768, K=768
    sgemm_tn_kernel<<<dim3(DIM / 128, TOKENS / 128), 256>>>(
        att_ptr, projw, out, TOKENS, DIM, DIM);
}

// round 4
// speedup vs baseline: 1.6805x; 1.6805x over previous
#include <cuda_runtime.h>
#include <math.h>
#include <stdint.h>

// Problem constants (fixed by setup_inputs)
#define BATCH   2
#define IMG     224
#define TOKENS  (BATCH*IMG*IMG)   // 100352
#define DIM     768
#define NH      12
#define HD      64
#define WS      7
#define L       (WS*WS)           // 49
#define NWIN    (BATCH*(IMG/WS)*(IMG/WS))  // 2048
#define SHIFT   3

// Scratch (device globals: allocation is forbidden in kernel_launch)
__device__ float g_qkv[(size_t)TOKENS * 3 * DIM];
__device__ float g_att[(size_t)TOKENS * DIM];
__device__ float g_sin[L * 32];
__device__ float g_cos[L * 32];

// ============================================================================
// helpers
// ============================================================================
__device__ __forceinline__ uint32_t smem_u32(const void* p) {
    uint32_t a;
    asm("{ .reg .u64 t; cvta.to.shared.u64 t, %1; cvt.u32.u64 %0, t; }" : "=r"(a) : "l"(p));
    return a;
}

// pack two fp32 -> bf16x2 (low = x, high = y), and the residual pair
__device__ __forceinline__ void split_pack(float x, float y, uint32_t& hi, uint32_t& lo) {
    asm("cvt.rn.bf16x2.f32 %0, %1, %2;" : "=r"(hi) : "f"(y), "f"(x));
    float hx = __uint_as_float(hi << 16);
    float hy = __uint_as_float(hi & 0xffff0000u);
    float lx = x - hx;
    float ly = y - hy;
    asm("cvt.rn.bf16x2.f32 %0, %1, %2;" : "=r"(lo) : "f"(ly), "f"(lx));
}

#define STSV2(addr, u0, u1) \
    asm volatile("st.shared.v2.b32 [%0], {%1,%2};" :: "r"(addr), "r"(u0), "r"(u1) : "memory")

#define LDSM4(r0, r1, r2, r3, addr) \
    asm volatile("ldmatrix.sync.aligned.m8n8.x4.shared.b16 {%0,%1,%2,%3}, [%4];" \
        : "=r"(r0), "=r"(r1), "=r"(r2), "=r"(r3) : "r"(addr))

#define MMA16816(d, a, b0, b1) \
    asm volatile("mma.sync.aligned.m16n8k16.row.col.f32.bf16.bf16.f32 " \
        "{%0,%1,%2,%3},{%4,%5,%6,%7},{%8,%9},{%0,%1,%2,%3};" \
        : "+f"((d)[0]), "+f"((d)[1]), "+f"((d)[2]), "+f"((d)[3]) \
        : "r"((a)[0]), "r"((a)[1]), "r"((a)[2]), "r"((a)[3]), "r"(b0), "r"(b1))

// ============================================================================
// RoPE tables
// ============================================================================
__global__ void rope_init_kernel() {
    for (int i = threadIdx.x; i < L * 32; i += blockDim.x) {
        int tok = i >> 5, d = i & 31;
        int ty = tok / WS, tx = tok - ty * WS;
        int f = d & 15;
        float inv = powf(100.0f, -((float)f) / 16.0f);
        float ang = ((d < 16) ? (float)ty : (float)tx) * inv;
        g_sin[i] = sinf(ang);
        g_cos[i] = cosf(ang);
    }
}

// ============================================================================
// 3x-BF16-split GEMM via mma.sync (HMMA tensor pipe):
//   C[M,N] = A[M,K] @ W[N,K]^T,  fp32 in/out, ~1e-5 accuracy.
// 128x128 CTA tile, BK=32, 256 threads (8 warps, 4x2), double-buffered smem.
// Requires M%128==0, N%128==0, K%32==0.
// ============================================================================
#define BM 128
#define BN 128
#define BK 32
#define PADB 80                 // smem row stride in BYTES (40 bf16) — LDSM conflict-free
#define TILE_B (128 * PADB)     // 10240 B per (operand,version) tile
#define BUF_B  (4 * TILE_B)     // Ahi,Alo,Bhi,Blo = 40960 B
#define SMEM_GEMM (2 * BUF_B)   // 81920 B

__global__ __launch_bounds__(256, 2) void gemm_bf16x3_kernel(
    const float* __restrict__ A, const float* __restrict__ W,
    float* __restrict__ C, int M, int N, int K)
{
    extern __shared__ char smem[];
    const uint32_t sb = smem_u32(smem);
    const int tid  = threadIdx.x;
    const int lane = tid & 31;
    const int wid  = tid >> 5;
    const int mtile = blockIdx.y, ntile = blockIdx.x;
    const int rm = (wid & 3) * 32;   // warp m base within tile
    const int nb = (wid >> 2) * 64;  // warp n base within tile

    const float* Abase = A + (size_t)mtile * BM * K;
    const float* Wbase = W + (size_t)ntile * BN * K;

    // per-thread gmem load slots: 4 float4 for A, 4 for B (128x32 fp32 each)
    int row[4], c4[4];
#pragma unroll
    for (int j = 0; j < 4; ++j) { int idx = tid + j * 256; row[j] = idx >> 3; c4[j] = idx & 7; }

    float4 ra[4], rb[4];
#pragma unroll
    for (int j = 0; j < 4; ++j) {
        ra[j] = *(const float4*)(Abase + (size_t)row[j] * K + c4[j] * 4);
        rb[j] = *(const float4*)(Wbase + (size_t)row[j] * K + c4[j] * 4);
    }

    float acc[2][8][4];
#pragma unroll
    for (int mt = 0; mt < 2; ++mt)
#pragma unroll
        for (int nt = 0; nt < 8; ++nt)
#pragma unroll
            for (int e = 0; e < 4; ++e) acc[mt][nt][e] = 0.0f;

    // ldmatrix per-lane address components (byte offsets within a tile)
    const uint32_t a_l = (uint32_t)((rm + (lane & 15)) * PADB + (lane >> 4) * 16);
    const uint32_t b_l = (uint32_t)((nb + (lane & 7) + ((lane >> 4) << 3)) * PADB
                                    + ((lane >> 3) & 1) * 16);

    const int NIT = K / BK;
    for (int it = 0; it < NIT; ++it) {
        const uint32_t so = sb + (uint32_t)(it & 1) * BUF_B;

        // ---- split + stage to smem ----
#pragma unroll
        for (int j = 0; j < 4; ++j) {
            uint32_t off = (uint32_t)(row[j] * PADB + c4[j] * 8);
            uint32_t h0, l0, h1, l1;
            split_pack(ra[j].x, ra[j].y, h0, l0);
            split_pack(ra[j].z, ra[j].w, h1, l1);
            STSV2(so + 0 * TILE_B + off, h0, h1);
            STSV2(so + 1 * TILE_B + off, l0, l1);
            split_pack(rb[j].x, rb[j].y, h0, l0);
            split_pack(rb[j].z, rb[j].w, h1, l1);
            STSV2(so + 2 * TILE_B + off, h0, h1);
            STSV2(so + 3 * TILE_B + off, l0, l1);
        }
        __syncthreads();

        // ---- prefetch next buffer ----
        if (it + 1 < NIT) {
            const int k0 = (it + 1) * BK;
#pragma unroll
            for (int j = 0; j < 4; ++j) {
                ra[j] = *(const float4*)(Abase + (size_t)row[j] * K + k0 + c4[j] * 4);
                rb[j] = *(const float4*)(Wbase + (size_t)row[j] * K + k0 + c4[j] * 4);
            }
        }

        // ---- MMA over this buffer ----
#pragma unroll
        for (int kk = 0; kk < 2; ++kk) {
            const uint32_t ao = so + kk * 32 + a_l;
            uint32_t ah[2][4], al[2][4];
            LDSM4(ah[0][0], ah[0][1], ah[0][2], ah[0][3], ao);
            LDSM4(ah[1][0], ah[1][1], ah[1][2], ah[1][3], ao + 16 * PADB);
            LDSM4(al[0][0], al[0][1], al[0][2], al[0][3], ao + TILE_B);
            LDSM4(al[1][0], al[1][1], al[1][2], al[1][3], ao + TILE_B + 16 * PADB);

            const uint32_t boh = so + 2 * TILE_B + kk * 32 + b_l;
            const uint32_t bol = so + 3 * TILE_B + kk * 32 + b_l;
#pragma unroll
            for (int nt2 = 0; nt2 < 4; ++nt2) {
                uint32_t bh[4], bl[4];
                LDSM4(bh[0], bh[1], bh[2], bh[3], boh + nt2 * (16 * PADB));
                LDSM4(bl[0], bl[1], bl[2], bl[3], bol + nt2 * (16 * PADB));
#pragma unroll
                for (int mt = 0; mt < 2; ++mt) {
                    MMA16816(acc[mt][2 * nt2],     ah[mt], bh[0], bh[1]);
                    MMA16816(acc[mt][2 * nt2],     ah[mt], bl[0], bl[1]);
                    MMA16816(acc[mt][2 * nt2],     al[mt], bh[0], bh[1]);
                    MMA16816(acc[mt][2 * nt2 + 1], ah[mt], bh[2], bh[3]);
                    MMA16816(acc[mt][2 * nt2 + 1], ah[mt], bl[2], bl[3]);
                    MMA16816(acc[mt][2 * nt2 + 1], al[mt], bh[2], bh[3]);
                }
            }
        }
        __syncthreads();
    }

    // ---- epilogue: fp32 stores ----
    const int crow  = mtile * BM + rm + (lane >> 2);
    const int ccol0 = ntile * BN + nb + (lane & 3) * 2;
#pragma unroll
    for (int mt = 0; mt < 2; ++mt) {
#pragma unroll
        for (int nt = 0; nt < 8; ++nt) {
            float* p = C + (size_t)(crow + mt * 16) * N + ccol0 + nt * 8;
            *(float2*)p            = make_float2(acc[mt][nt][0], acc[mt][nt][1]);
            *(float2*)(p + 8 * (size_t)N) = make_float2(acc[mt][nt][2], acc[mt][nt][3]);
        }
    }
}

// ============================================================================
// Window attention: one block per (head, window). 64 threads.
// ============================================================================
__global__ __launch_bounds__(64) void window_attn_kernel(
    const float* __restrict__ qkv, float* __restrict__ outp)
{
    __shared__ __align__(16) float Qs[L * 68];
    __shared__ __align__(16) float Ks[L * 64];
    __shared__ __align__(16) float Vs[L * 64];
    __shared__ float S[L * L];
    __shared__ float kscale[L];
    __shared__ int   grows[L];

    const int h   = blockIdx.x;
    const int w   = blockIdx.y;
    const int tid = threadIdx.x;
    const int b   = w >> 10;
    const int rem = w & 1023;
    const int wh  = rem >> 5, ww = rem & 31;

    if (tid < L) {
        int ty = tid / WS, tx = tid - ty * WS;
        int y = wh * WS + ty + SHIFT; if (y >= IMG) y -= IMG;
        int x = ww * WS + tx + SHIFT; if (x >= IMG) x -= IMG;
        grows[tid] = b * (IMG * IMG) + y * IMG + x;
    }
    __syncthreads();

    const int lane = tid & 31;
    const int warp = tid >> 5;

    for (int t = 0; t < L; ++t) {
        size_t base = (size_t)grows[t] * (3 * DIM) + h * HD;
        float s = g_sin[t * 32 + lane];
        float c = g_cos[t * 32 + lane];
        if (warp == 0) {
            float t1 = qkv[base + lane];
            float t2 = qkv[base + lane + 32];
            Qs[t * 68 + lane]      = t1 * c - t2 * s;
            Qs[t * 68 + lane + 32] = t1 * s + t2 * c;
        } else {
            float t1 = qkv[base + DIM + lane];
            float t2 = qkv[base + DIM + lane + 32];
            float r1 = t1 * c - t2 * s;
            float r2 = t1 * s + t2 * c;
            Ks[t * 64 + lane]      = r1;
            Ks[t * 64 + lane + 32] = r2;
            float ssq = r1 * r1 + r2 * r2;
#pragma unroll
            for (int off = 16; off; off >>= 1)
                ssq += __shfl_xor_sync(0xffffffffu, ssq, off);
            if (lane == 0) kscale[t] = 1.0f / fmaxf(sqrtf(ssq), 1e-12f);
        }
    }
    for (int t = 0; t < L; ++t) {
        size_t base = (size_t)grows[t] * (3 * DIM) + h * HD + 2 * DIM;
        Vs[t * 64 + tid] = qkv[base + tid];
    }
    __syncthreads();

    if (tid < L) {
        const int i = tid;
        float4 qv[16];
#pragma unroll
        for (int d4 = 0; d4 < 16; ++d4)
            qv[d4] = *(const float4*)&Qs[i * 68 + d4 * 4];

        float ssq = 0.0f;
#pragma unroll
        for (int d4 = 0; d4 < 16; ++d4)
            ssq += qv[d4].x * qv[d4].x + qv[d4].y * qv[d4].y
                 + qv[d4].z * qv[d4].z + qv[d4].w * qv[d4].w;
        float qsc = 1.0f / fmaxf(sqrtf(ssq), 1e-12f);

        float mx = -1e30f;
        for (int j = 0; j < L; ++j) {
            float d0 = 0.f, d1 = 0.f, d2 = 0.f, d3 = 0.f;
#pragma unroll
            for (int d4 = 0; d4 < 16; ++d4) {
                float4 k4 = *(const float4*)&Ks[j * 64 + d4 * 4];
                d0 += qv[d4].x * k4.x; d1 += qv[d4].y * k4.y;
                d2 += qv[d4].z * k4.z; d3 += qv[d4].w * k4.w;
            }
            float logit = (d0 + d1 + d2 + d3) * (qsc * kscale[j] * 100.0f);
            S[i * L + j] = logit;
            mx = fmaxf(mx, logit);
        }
        float sum = 0.0f;
        for (int j = 0; j < L; ++j) {
            float e = __expf(S[i * L + j] - mx);
            S[i * L + j] = e;
            sum += e;
        }

        float ov[64];
#pragma unroll
        for (int d = 0; d < 64; ++d) ov[d] = 0.0f;
        for (int j = 0; j < L; ++j) {
            float wgt = S[i * L + j];
#pragma unroll
            for (int d4 = 0; d4 < 16; ++d4) {
                float4 v4 = *(const float4*)&Vs[j * 64 + d4 * 4];
                ov[d4 * 4 + 0] += wgt * v4.x;
                ov[d4 * 4 + 1] += wgt * v4.y;
                ov[d4 * 4 + 2] += wgt * v4.z;
                ov[d4 * 4 + 3] += wgt * v4.w;
            }
        }
        float isum = 1.0f / sum;
#pragma unroll
        for (int d = 0; d < 64; ++d) Qs[i * 68 + d] = ov[d] * isum;
    }
    __syncthreads();

    for (int t = 0; t < L; ++t)
        outp[(size_t)grows[t] * DIM + h * HD + tid] = Qs[t * 68 + tid];
}

// ---------------------------------------------------------------------------
extern "C" void kernel_launch(void* const* d_in, const int* in_sizes, int n_in,
                              void* d_out, int out_size)
{
    const float* x     = (const float*)d_in[0];
    const float* qkv_w = (const float*)d_in[1];
    const float* projw = (const float*)d_in[2];
    float* out = (float*)d_out;

    float *qkv_ptr, *att_ptr;
    cudaGetSymbolAddress((void**)&qkv_ptr, g_qkv);
    cudaGetSymbolAddress((void**)&att_ptr, g_att);

    cudaFuncSetAttribute(gemm_bf16x3_kernel,
                         cudaFuncAttributeMaxDynamicSharedMemorySize, SMEM_GEMM);

    rope_init_kernel<<<1, 256>>>();

    // qkv = x @ qkv_w^T : M=100352, N=2304, K=768
    gemm_bf16x3_kernel<<<dim3(3 * DIM / BN, TOKENS / BM), 256, SMEM_GEMM>>>(
        x, qkv_w, qkv_ptr, TOKENS, 3 * DIM, DIM);

    // windowed attention
    window_attn_kernel<<<dim3(NH, NWIN), 64>>>(qkv_ptr, att_ptr);

    // out = att @ proj_w^T : M=100352, N=768, K=768
    gemm_bf16x3_kernel<<<dim3(DIM / BN, TOKENS / BM), 256, SMEM_GEMM>>>(
        att_ptr, projw, out, TOKENS, DIM, DIM);
}

// round 5
// speedup vs baseline: 1.9106x; 1.1369x over previous
#include <cuda_runtime.h>
#include <math.h>
#include <stdint.h>

// Problem constants (fixed by setup_inputs)
#define BATCH   2
#define IMG     224
#define TOKENS  (BATCH*IMG*IMG)   // 100352
#define DIM     768
#define NH      12
#define HD      64
#define WS      7
#define L       (WS*WS)           // 49
#define NWIN    (BATCH*(IMG/WS)*(IMG/WS))  // 2048
#define SHIFT   3

// Scratch (device globals: allocation is forbidden in kernel_launch)
__device__ float g_qkv[(size_t)TOKENS * 3 * DIM];
__device__ float g_att[(size_t)TOKENS * DIM];
__device__ float g_sin[L * 32];
__device__ float g_cos[L * 32];

// ============================================================================
// helpers
// ============================================================================
__device__ __forceinline__ uint32_t smem_u32(const void* p) {
    uint32_t a;
    asm("{ .reg .u64 t; cvta.to.shared.u64 t, %1; cvt.u32.u64 %0, t; }" : "=r"(a) : "l"(p));
    return a;
}

// pack two fp32 -> bf16x2 (low = x, high = y), and the residual pair
__device__ __forceinline__ void split_pack(float x, float y, uint32_t& hi, uint32_t& lo) {
    asm("cvt.rn.bf16x2.f32 %0, %1, %2;" : "=r"(hi) : "f"(y), "f"(x));
    float hx = __uint_as_float(hi << 16);
    float hy = __uint_as_float(hi & 0xffff0000u);
    float lx = x - hx;
    float ly = y - hy;
    asm("cvt.rn.bf16x2.f32 %0, %1, %2;" : "=r"(lo) : "f"(ly), "f"(lx));
}

#define STSV4(addr, u0, u1, u2, u3) \
    asm volatile("st.shared.v4.b32 [%0], {%1,%2,%3,%4};" \
        :: "r"(addr), "r"(u0), "r"(u1), "r"(u2), "r"(u3) : "memory")

#define LDSM4(r, addr) \
    asm volatile("ldmatrix.sync.aligned.m8n8.x4.shared.b16 {%0,%1,%2,%3}, [%4];" \
        : "=r"((r)[0]), "=r"((r)[1]), "=r"((r)[2]), "=r"((r)[3]) : "r"(addr))

#define MMA16816(d, a, b0, b1) \
    asm volatile("mma.sync.aligned.m16n8k16.row.col.f32.bf16.bf16.f32 " \
        "{%0,%1,%2,%3},{%4,%5,%6,%7},{%8,%9},{%0,%1,%2,%3};" \
        : "+f"((d)[0]), "+f"((d)[1]), "+f"((d)[2]), "+f"((d)[3]) \
        : "r"((a)[0]), "r"((a)[1]), "r"((a)[2]), "r"((a)[3]), "r"(b0), "r"(b1))

// ============================================================================
// RoPE tables
// ============================================================================
__global__ void rope_init_kernel() {
    for (int i = threadIdx.x; i < L * 32; i += blockDim.x) {
        int tok = i >> 5, d = i & 31;
        int ty = tok / WS, tx = tok - ty * WS;
        int f = d & 15;
        float inv = powf(100.0f, -((float)f) / 16.0f);
        float ang = ((d < 16) ? (float)ty : (float)tx) * inv;
        g_sin[i] = sinf(ang);
        g_cos[i] = cosf(ang);
    }
}

// ============================================================================
// 3x-BF16-split GEMM via mma.sync (HMMA):
//   C[M,N] = A[M,K] @ W[N,K]^T,  fp32 in/out, ~1e-5 accuracy.
// CTA tile 128x256, BK=16, 256 threads (8 warps, 2x4), warp tile 64x64,
// double-buffered smem, one barrier per k-iteration.
// Requires M%128==0, N%256==0, K%16==0.
// ============================================================================
#define BM 128
#define BN 256
#define BK 16
#define PADB 48                   // bytes per 16-bf16 row (32B data + 16B pad)
#define A_LO  6144u               // 128*48
#define B_HI  12288u
#define B_LO  24576u              // B_HI + 256*48
#define BUF_B 36864u
#define SMEM_GEMM (2u * BUF_B)    // 73728

__global__ __launch_bounds__(256, 1) void gemm_bf16x3_kernel(
    const float* __restrict__ A, const float* __restrict__ W,
    float* __restrict__ C, int M, int N, int K)
{
    extern __shared__ char smem[];
    const uint32_t sb = smem_u32(smem);
    const int tid  = threadIdx.x;
    const int lane = tid & 31;
    const int wid  = tid >> 5;
    const int mtile = blockIdx.y, ntile = blockIdx.x;
    const int rm = (wid & 1) * 64;    // warp m base (2 warps down)
    const int nb = (wid >> 1) * 64;   // warp n base (4 warps across)

    const float* Abase = A + (size_t)mtile * BM * K;
    const float* Wbase = W + (size_t)ntile * BN * K;

    // staging slots: 8 consecutive fp32 per slot.  A: 1 slot, B: 2 slots.
    const int arow  = tid >> 1, ahalf = tid & 1;
    const int brow0 = tid >> 1, bhalf = tid & 1;   // brow1 = brow0 + 128

    const float* aptr  = Abase + (size_t)arow  * K + ahalf * 8;
    const float* bptr0 = Wbase + (size_t)brow0 * K + bhalf * 8;
    const float* bptr1 = bptr0 + (size_t)128 * K;

    const uint32_t sA  = sb + (uint32_t)(arow  * PADB + ahalf * 16);
    const uint32_t sB0 = sb + B_HI + (uint32_t)(brow0 * PADB + bhalf * 16);
    const uint32_t sB1 = sB0 + 128u * PADB;

    float4 ra0, ra1, rb00, rb01, rb10, rb11;
    ra0  = *(const float4*)(aptr);      ra1  = *(const float4*)(aptr + 4);
    rb00 = *(const float4*)(bptr0);     rb01 = *(const float4*)(bptr0 + 4);
    rb10 = *(const float4*)(bptr1);     rb11 = *(const float4*)(bptr1 + 4);

    float acc[4][8][4];
#pragma unroll
    for (int mt = 0; mt < 4; ++mt)
#pragma unroll
        for (int nt = 0; nt < 8; ++nt)
#pragma unroll
            for (int e = 0; e < 4; ++e) acc[mt][nt][e] = 0.0f;

    // ldmatrix lane addresses (within a buffer)
    const uint32_t a_l = sb + (uint32_t)((rm + (lane & 15)) * PADB + (lane >> 4) * 16);
    const uint32_t b_l = sb + B_HI + (uint32_t)((nb + (lane & 7) + ((lane >> 4) << 3)) * PADB
                                                + ((lane >> 3) & 1) * 16);

    const int NIT = K / BK;   // 48
    for (int it = 0; it < NIT; ++it) {
        const uint32_t so = (uint32_t)(it & 1) * BUF_B;

        // ---- split + stage (STS.128, hi and lo tiles) ----
        {
            uint32_t h0, h1, h2, h3, l0, l1, l2, l3;
            split_pack(ra0.x, ra0.y, h0, l0); split_pack(ra0.z, ra0.w, h1, l1);
            split_pack(ra1.x, ra1.y, h2, l2); split_pack(ra1.z, ra1.w, h3, l3);
            STSV4(sA + so,        h0, h1, h2, h3);
            STSV4(sA + so + A_LO, l0, l1, l2, l3);
            split_pack(rb00.x, rb00.y, h0, l0); split_pack(rb00.z, rb00.w, h1, l1);
            split_pack(rb01.x, rb01.y, h2, l2); split_pack(rb01.z, rb01.w, h3, l3);
            STSV4(sB0 + so,                  h0, h1, h2, h3);
            STSV4(sB0 + so + (B_LO - B_HI),  l0, l1, l2, l3);
            split_pack(rb10.x, rb10.y, h0, l0); split_pack(rb10.z, rb10.w, h1, l1);
            split_pack(rb11.x, rb11.y, h2, l2); split_pack(rb11.z, rb11.w, h3, l3);
            STSV4(sB1 + so,                  h0, h1, h2, h3);
            STSV4(sB1 + so + (B_LO - B_HI),  l0, l1, l2, l3);
        }
        __syncthreads();

        // ---- prefetch next k-slice ----
        if (it + 1 < NIT) {
            const int k0 = (it + 1) * BK;
            ra0  = *(const float4*)(aptr  + k0);     ra1  = *(const float4*)(aptr  + k0 + 4);
            rb00 = *(const float4*)(bptr0 + k0);     rb01 = *(const float4*)(bptr0 + k0 + 4);
            rb10 = *(const float4*)(bptr1 + k0);     rb11 = *(const float4*)(bptr1 + k0 + 4);
        }

        // ---- A fragments (hi+lo for 4 m16 tiles) ----
        uint32_t ah[4][4], al[4][4];
#pragma unroll
        for (int mt = 0; mt < 4; ++mt) {
            LDSM4(ah[mt], a_l + so + mt * (16 * PADB));
            LDSM4(al[mt], a_l + so + A_LO + mt * (16 * PADB));
        }

        // ---- B in two halves of 32 columns; term-major MMA interleave ----
#pragma unroll
        for (int half = 0; half < 2; ++half) {
            uint32_t bh[2][4], bl[2][4];
#pragma unroll
            for (int q = 0; q < 2; ++q) {
                const int nt2 = half * 2 + q;
                LDSM4(bh[q], b_l + so + nt2 * (16 * PADB));
                LDSM4(bl[q], b_l + so + (B_LO - B_HI) + nt2 * (16 * PADB));
            }
            // term 1: ah * bh
#pragma unroll
            for (int mt = 0; mt < 4; ++mt)
#pragma unroll
                for (int q = 0; q < 2; ++q) {
                    MMA16816(acc[mt][half * 4 + 2 * q],     ah[mt], bh[q][0], bh[q][1]);
                    MMA16816(acc[mt][half * 4 + 2 * q + 1], ah[mt], bh[q][2], bh[q][3]);
                }
            // term 2: ah * bl
#pragma unroll
            for (int mt = 0; mt < 4; ++mt)
#pragma unroll
                for (int q = 0; q < 2; ++q) {
                    MMA16816(acc[mt][half * 4 + 2 * q],     ah[mt], bl[q][0], bl[q][1]);
                    MMA16816(acc[mt][half * 4 + 2 * q + 1], ah[mt], bl[q][2], bl[q][3]);
                }
            // term 3: al * bh
#pragma unroll
            for (int mt = 0; mt < 4; ++mt)
#pragma unroll
                for (int q = 0; q < 2; ++q) {
                    MMA16816(acc[mt][half * 4 + 2 * q],     al[mt], bh[q][0], bh[q][1]);
                    MMA16816(acc[mt][half * 4 + 2 * q + 1], al[mt], bh[q][2], bh[q][3]);
                }
        }
    }

    // ---- epilogue: fp32 stores ----
    const int rowb = mtile * BM + rm + (lane >> 2);
    const int colb = ntile * BN + nb + (lane & 3) * 2;
#pragma unroll
    for (int mt = 0; mt < 4; ++mt) {
#pragma unroll
        for (int nt = 0; nt < 8; ++nt) {
            float* p = C + (size_t)(rowb + mt * 16) * N + colb + nt * 8;
            *(float2*)p                    = make_float2(acc[mt][nt][0], acc[mt][nt][1]);
            *(float2*)(p + 8 * (size_t)N)  = make_float2(acc[mt][nt][2], acc[mt][nt][3]);
        }
    }
}

// ============================================================================
// Window attention: one block per (head, window). 64 threads.
// ============================================================================
__global__ __launch_bounds__(64) void window_attn_kernel(
    const float* __restrict__ qkv, float* __restrict__ outp)
{
    __shared__ __align__(16) float Qs[L * 68];
    __shared__ __align__(16) float Ks[L * 64];
    __shared__ __align__(16) float Vs[L * 64];
    __shared__ float S[L * L];
    __shared__ float kscale[L];
    __shared__ int   grows[L];

    const int h   = blockIdx.x;
    const int w   = blockIdx.y;
    const int tid = threadIdx.x;
    const int b   = w >> 10;
    const int rem = w & 1023;
    const int wh  = rem >> 5, ww = rem & 31;

    if (tid < L) {
        int ty = tid / WS, tx = tid - ty * WS;
        int y = wh * WS + ty + SHIFT; if (y >= IMG) y -= IMG;
        int x = ww * WS + tx + SHIFT; if (x >= IMG) x -= IMG;
        grows[tid] = b * (IMG * IMG) + y * IMG + x;
    }
    __syncthreads();

    const int lane = tid & 31;
    const int warp = tid >> 5;

    for (int t = 0; t < L; ++t) {
        size_t base = (size_t)grows[t] * (3 * DIM) + h * HD;
        float s = g_sin[t * 32 + lane];
        float c = g_cos[t * 32 + lane];
        if (warp == 0) {
            float t1 = qkv[base + lane];
            float t2 = qkv[base + lane + 32];
            Qs[t * 68 + lane]      = t1 * c - t2 * s;
            Qs[t * 68 + lane + 32] = t1 * s + t2 * c;
        } else {
            float t1 = qkv[base + DIM + lane];
            float t2 = qkv[base + DIM + lane + 32];
            float r1 = t1 * c - t2 * s;
            float r2 = t1 * s + t2 * c;
            Ks[t * 64 + lane]      = r1;
            Ks[t * 64 + lane + 32] = r2;
            float ssq = r1 * r1 + r2 * r2;
#pragma unroll
            for (int off = 16; off; off >>= 1)
                ssq += __shfl_xor_sync(0xffffffffu, ssq, off);
            if (lane == 0) kscale[t] = 1.0f / fmaxf(sqrtf(ssq), 1e-12f);
        }
    }
    for (int t = 0; t < L; ++t) {
        size_t base = (size_t)grows[t] * (3 * DIM) + h * HD + 2 * DIM;
        Vs[t * 64 + tid] = qkv[base + tid];
    }
    __syncthreads();

    if (tid < L) {
        const int i = tid;
        float4 qv[16];
#pragma unroll
        for (int d4 = 0; d4 < 16; ++d4)
            qv[d4] = *(const float4*)&Qs[i * 68 + d4 * 4];

        float ssq = 0.0f;
#pragma unroll
        for (int d4 = 0; d4 < 16; ++d4)
            ssq += qv[d4].x * qv[d4].x + qv[d4].y * qv[d4].y
                 + qv[d4].z * qv[d4].z + qv[d4].w * qv[d4].w;
        float qsc = 1.0f / fmaxf(sqrtf(ssq), 1e-12f);

        float mx = -1e30f;
        for (int j = 0; j < L; ++j) {
            float d0 = 0.f, d1 = 0.f, d2 = 0.f, d3 = 0.f;
#pragma unroll
            for (int d4 = 0; d4 < 16; ++d4) {
                float4 k4 = *(const float4*)&Ks[j * 64 + d4 * 4];
                d0 += qv[d4].x * k4.x; d1 += qv[d4].y * k4.y;
                d2 += qv[d4].z * k4.z; d3 += qv[d4].w * k4.w;
            }
            float logit = (d0 + d1 + d2 + d3) * (qsc * kscale[j] * 100.0f);
            S[i * L + j] = logit;
            mx = fmaxf(mx, logit);
        }
        float sum = 0.0f;
        for (int j = 0; j < L; ++j) {
            float e = __expf(S[i * L + j] - mx);
            S[i * L + j] = e;
            sum += e;
        }

        float ov[64];
#pragma unroll
        for (int d = 0; d < 64; ++d) ov[d] = 0.0f;
        for (int j = 0; j < L; ++j) {
            float wgt = S[i * L + j];
#pragma unroll
            for (int d4 = 0; d4 < 16; ++d4) {
                float4 v4 = *(const float4*)&Vs[j * 64 + d4 * 4];
                ov[d4 * 4 + 0] += wgt * v4.x;
                ov[d4 * 4 + 1] += wgt * v4.y;
                ov[d4 * 4 + 2] += wgt * v4.z;
                ov[d4 * 4 + 3] += wgt * v4.w;
            }
        }
        float isum = 1.0f / sum;
#pragma unroll
        for (int d = 0; d < 64; ++d) Qs[i * 68 + d] = ov[d] * isum;
    }
    __syncthreads();

    for (int t = 0; t < L; ++t)
        outp[(size_t)grows[t] * DIM + h * HD + tid] = Qs[t * 68 + tid];
}

// ---------------------------------------------------------------------------
extern "C" void kernel_launch(void* const* d_in, const int* in_sizes, int n_in,
                              void* d_out, int out_size)
{
    const float* x     = (const float*)d_in[0];
    const float* qkv_w = (const float*)d_in[1];
    const float* projw = (const float*)d_in[2];
    float* out = (float*)d_out;

    float *qkv_ptr, *att_ptr;
    cudaGetSymbolAddress((void**)&qkv_ptr, g_qkv);
    cudaGetSymbolAddress((void**)&att_ptr, g_att);

    cudaFuncSetAttribute(gemm_bf16x3_kernel,
                         cudaFuncAttributeMaxDynamicSharedMemorySize, SMEM_GEMM);

    rope_init_kernel<<<1, 256>>>();

    // qkv = x @ qkv_w^T : M=100352, N=2304, K=768
    gemm_bf16x3_kernel<<<dim3(3 * DIM / BN, TOKENS / BM), 256, SMEM_GEMM>>>(
        x, qkv_w, qkv_ptr, TOKENS, 3 * DIM, DIM);

    // windowed attention
    window_attn_kernel<<<dim3(NH, NWIN), 64>>>(qkv_ptr, att_ptr);

    // out = att @ proj_w^T : M=100352, N=768, K=768
    gemm_bf16x3_kernel<<<dim3(DIM / BN, TOKENS / BM), 256, SMEM_GEMM>>>(
        att_ptr, projw, out, TOKENS, DIM, DIM);
}

// round 6
// speedup vs baseline: 2.4007x; 1.2565x over previous
#include <cuda_runtime.h>
#include <math.h>
#include <stdint.h>

// Problem constants (fixed by setup_inputs)
#define BATCH   2
#define IMG     224
#define TOKENS  (BATCH*IMG*IMG)   // 100352
#define DIM     768
#define NH      12
#define HD      64
#define WS      7
#define L       (WS*WS)           // 49
#define NWIN    (BATCH*(IMG/WS)*(IMG/WS))  // 2048
#define SHIFT   3

// Scratch (device globals: allocation is forbidden in kernel_launch)
__device__ float    g_qkv[(size_t)TOKENS * 3 * DIM];
__device__ uint16_t g_xhi[(size_t)TOKENS * DIM];
__device__ uint16_t g_xlo[(size_t)TOKENS * DIM];
__device__ uint16_t g_qwhi[(size_t)3 * DIM * DIM];
__device__ uint16_t g_qwlo[(size_t)3 * DIM * DIM];
__device__ uint16_t g_pwhi[(size_t)DIM * DIM];
__device__ uint16_t g_pwlo[(size_t)DIM * DIM];
__device__ uint16_t g_atthi[(size_t)TOKENS * DIM];
__device__ uint16_t g_attlo[(size_t)TOKENS * DIM];
__device__ float    g_sin[L * 32];
__device__ float    g_cos[L * 32];

// ============================================================================
// helpers
// ============================================================================
__device__ __forceinline__ uint32_t smem_u32(const void* p) {
    uint32_t a;
    asm("{ .reg .u64 t; cvta.to.shared.u64 t, %1; cvt.u32.u64 %0, t; }" : "=r"(a) : "l"(p));
    return a;
}

// pack two fp32 -> bf16x2 (low 16 bits = x, high = y), plus residual pair
__device__ __forceinline__ void split_pack(float x, float y, uint32_t& hi, uint32_t& lo) {
    asm("cvt.rn.bf16x2.f32 %0, %1, %2;" : "=r"(hi) : "f"(y), "f"(x));
    float hx = __uint_as_float(hi << 16);
    float hy = __uint_as_float(hi & 0xffff0000u);
    float lx = x - hx;
    float ly = y - hy;
    asm("cvt.rn.bf16x2.f32 %0, %1, %2;" : "=r"(lo) : "f"(ly), "f"(lx));
}

// single fp32 -> bf16 hi + bf16 residual
__device__ __forceinline__ void split1(float x, uint16_t& h, uint16_t& l) {
    uint16_t hh;
    asm("cvt.rn.bf16.f32 %0, %1;" : "=h"(hh) : "f"(x));
    float hf = __uint_as_float(((uint32_t)hh) << 16);
    asm("cvt.rn.bf16.f32 %0, %1;" : "=h"(l) : "f"(x - hf));
    h = hh;
}

#define CPA16(dst, src) \
    asm volatile("cp.async.cg.shared.global [%0], [%1], 16;" :: "r"(dst), "l"(src) : "memory")
#define CPA_COMMIT() asm volatile("cp.async.commit_group;" ::: "memory")
#define CPA_WAIT2()  asm volatile("cp.async.wait_group 2;" ::: "memory")

#define LDSM4(r, addr) \
    asm volatile("ldmatrix.sync.aligned.m8n8.x4.shared.b16 {%0,%1,%2,%3}, [%4];" \
        : "=r"((r)[0]), "=r"((r)[1]), "=r"((r)[2]), "=r"((r)[3]) : "r"(addr))

#define MMA16816(d, a, b0, b1) \
    asm volatile("mma.sync.aligned.m16n8k16.row.col.f32.bf16.bf16.f32 " \
        "{%0,%1,%2,%3},{%4,%5,%6,%7},{%8,%9},{%0,%1,%2,%3};" \
        : "+f"((d)[0]), "+f"((d)[1]), "+f"((d)[2]), "+f"((d)[3]) \
        : "r"((a)[0]), "r"((a)[1]), "r"((a)[2]), "r"((a)[3]), "r"(b0), "r"(b1))

// ============================================================================
// RoPE tables
// ============================================================================
__global__ void rope_init_kernel() {
    for (int i = threadIdx.x; i < L * 32; i += blockDim.x) {
        int tok = i >> 5, d = i & 31;
        int ty = tok / WS, tx = tok - ty * WS;
        int f = d & 15;
        float inv = powf(100.0f, -((float)f) / 16.0f);
        float ang = ((d < 16) ? (float)ty : (float)tx) * inv;
        g_sin[i] = sinf(ang);
        g_cos[i] = cosf(ang);
    }
}

// ============================================================================
// fp32 -> bf16 hi/lo split pre-pass (vectorized, grid-stride)
// ============================================================================
__global__ void split_kernel(const float* __restrict__ src,
                             uint16_t* __restrict__ hi, uint16_t* __restrict__ lo,
                             size_t n4)
{
    size_t idx = (size_t)blockIdx.x * blockDim.x + threadIdx.x;
    size_t stride = (size_t)gridDim.x * blockDim.x;
    for (; idx < n4; idx += stride) {
        float4 v = ((const float4*)src)[idx];
        uint32_t h0, l0, h1, l1;
        split_pack(v.x, v.y, h0, l0);
        split_pack(v.z, v.w, h1, l1);
        ((uint2*)hi)[idx] = make_uint2(h0, h1);
        ((uint2*)lo)[idx] = make_uint2(l0, l1);
    }
}

// ============================================================================
// 3x-BF16-split GEMM, pre-split bf16 hi/lo operands, cp.async 4-stage:
//   C[M,N] = A[M,K] @ W[N,K]^T  (fp32 out)
// CTA tile 128x256, BK=16, 256 threads (8 warps, 2x4, warp tile 64x64).
// Requires M%128==0, N%256==0, K%16==0.
// ============================================================================
#define BM 128
#define BN 256
#define BK 16
#define PADB 48
#define A_LO  6144u
#define B_HI  12288u
#define B_LO  24576u
#define BUF_B 36864u
#define STAGES 4
#define SMEM_GEMM (STAGES * BUF_B)   // 147456

__global__ __launch_bounds__(256, 1) void gemm_presplit_kernel(
    const uint16_t* __restrict__ Ahi, const uint16_t* __restrict__ Alo,
    const uint16_t* __restrict__ Bhi, const uint16_t* __restrict__ Blo,
    float* __restrict__ C, int M, int N, int K)
{
    extern __shared__ char smem[];
    const uint32_t sb = smem_u32(smem);
    const int tid  = threadIdx.x;
    const int lane = tid & 31;
    const int wid  = tid >> 5;
    const int mtile = blockIdx.y, ntile = blockIdx.x;
    const int rm = (wid & 1) * 64;
    const int nb = (wid >> 1) * 64;

    // cp.async source pointers (bf16 elements)
    const int arow = tid >> 1, ahalf = tid & 1;
    const uint16_t* pAhi = Ahi + (size_t)(mtile * BM + arow) * K + ahalf * 8;
    const uint16_t* pAlo = Alo + (size_t)(mtile * BM + arow) * K + ahalf * 8;
    const uint16_t* pBhi = Bhi + (size_t)(ntile * BN + arow) * K + ahalf * 8;
    const uint16_t* pBlo = Blo + (size_t)(ntile * BN + arow) * K + ahalf * 8;
    const size_t bstep = (size_t)128 * K;

    const uint32_t dA = sb + (uint32_t)(arow * PADB + ahalf * 16);
    const uint32_t dB = sb + B_HI + (uint32_t)(arow * PADB + ahalf * 16);

    auto issue = [&](int s) {
        const uint32_t off = (uint32_t)(s & 3) * BUF_B;
        const int k0 = s * BK;
        CPA16(dA + off,                              pAhi + k0);
        CPA16(dA + off + A_LO,                       pAlo + k0);
        CPA16(dB + off,                              pBhi + k0);
        CPA16(dB + off + 128u * PADB,                pBhi + bstep + k0);
        CPA16(dB + off + (B_LO - B_HI),              pBlo + k0);
        CPA16(dB + off + (B_LO - B_HI) + 128u * PADB, pBlo + bstep + k0);
        CPA_COMMIT();
    };

    float acc[4][8][4];
#pragma unroll
    for (int mt = 0; mt < 4; ++mt)
#pragma unroll
        for (int nt = 0; nt < 8; ++nt)
#pragma unroll
            for (int e = 0; e < 4; ++e) acc[mt][nt][e] = 0.0f;

    // ldmatrix lane addresses (within a buffer)
    const uint32_t a_l = sb + (uint32_t)((rm + (lane & 15)) * PADB + (lane >> 4) * 16);
    const uint32_t b_l = sb + B_HI + (uint32_t)((nb + (lane & 7) + ((lane >> 4) << 3)) * PADB
                                                + ((lane >> 3) & 1) * 16);

    const int NIT = K / BK;   // 48
    issue(0); issue(1); issue(2);

    for (int it = 0; it < NIT; ++it) {
        CPA_WAIT2();
        __syncthreads();
        const uint32_t so = (uint32_t)(it & 3) * BUF_B;

        uint32_t ah[4][4], al[4][4];
#pragma unroll
        for (int mt = 0; mt < 4; ++mt) {
            LDSM4(ah[mt], a_l + so + mt * (16 * PADB));
            LDSM4(al[mt], a_l + so + A_LO + mt * (16 * PADB));
        }

#pragma unroll
        for (int half = 0; half < 2; ++half) {
            uint32_t bh[2][4], bl[2][4];
#pragma unroll
            for (int q = 0; q < 2; ++q) {
                const int nt2 = half * 2 + q;
                LDSM4(bh[q], b_l + so + nt2 * (16 * PADB));
                LDSM4(bl[q], b_l + so + (B_LO - B_HI) + nt2 * (16 * PADB));
            }
#pragma unroll
            for (int mt = 0; mt < 4; ++mt)
#pragma unroll
                for (int q = 0; q < 2; ++q) {
                    MMA16816(acc[mt][half * 4 + 2 * q],     ah[mt], bh[q][0], bh[q][1]);
                    MMA16816(acc[mt][half * 4 + 2 * q + 1], ah[mt], bh[q][2], bh[q][3]);
                }
#pragma unroll
            for (int mt = 0; mt < 4; ++mt)
#pragma unroll
                for (int q = 0; q < 2; ++q) {
                    MMA16816(acc[mt][half * 4 + 2 * q],     ah[mt], bl[q][0], bl[q][1]);
                    MMA16816(acc[mt][half * 4 + 2 * q + 1], ah[mt], bl[q][2], bl[q][3]);
                }
#pragma unroll
            for (int mt = 0; mt < 4; ++mt)
#pragma unroll
                for (int q = 0; q < 2; ++q) {
                    MMA16816(acc[mt][half * 4 + 2 * q],     al[mt], bh[q][0], bh[q][1]);
                    MMA16816(acc[mt][half * 4 + 2 * q + 1], al[mt], bh[q][2], bh[q][3]);
                }
        }

        if (it + 3 < NIT) issue(it + 3);
        else CPA_COMMIT();   // empty group keeps wait_group count uniform
    }

    // ---- epilogue: fp32 stores ----
    const int rowb = mtile * BM + rm + (lane >> 2);
    const int colb = ntile * BN + nb + (lane & 3) * 2;
#pragma unroll
    for (int mt = 0; mt < 4; ++mt) {
#pragma unroll
        for (int nt = 0; nt < 8; ++nt) {
            float* p = C + (size_t)(rowb + mt * 16) * N + colb + nt * 8;
            *(float2*)p                   = make_float2(acc[mt][nt][0], acc[mt][nt][1]);
            *(float2*)(p + 8 * (size_t)N) = make_float2(acc[mt][nt][2], acc[mt][nt][3]);
        }
    }
}

// ============================================================================
// Window attention: one block per (head, window), 128 threads (4 warps).
// Load phase: 147 row tasks split across warps (RoPE inline, no reductions).
// Norms from smem; scores/AV with 98 threads (2 per row).
// Output written directly as bf16 hi/lo (feeds the proj GEMM).
// ============================================================================
__global__ __launch_bounds__(128) void window_attn_kernel(
    const float* __restrict__ qkv,
    uint16_t* __restrict__ atthi, uint16_t* __restrict__ attlo)
{
    __shared__ __align__(16) float Qs[L * 68];
    __shared__ __align__(16) float Ks[L * 68];
    __shared__ __align__(16) float Vs[L * 64];
    __shared__ float S[L * 52];
    __shared__ float qn[L], kn[L];
    __shared__ int grows[L];

    const int h   = blockIdx.x;
    const int w   = blockIdx.y;
    const int tid = threadIdx.x;
    const int lane = tid & 31;
    const int warp = tid >> 5;
    const int b   = w >> 10;
    const int rem = w & 1023;
    const int wh  = rem >> 5, ww = rem & 31;

    if (tid < L) {
        int ty = tid / WS, tx = tid - ty * WS;
        int y = wh * WS + ty + SHIFT; if (y >= IMG) y -= IMG;
        int x = ww * WS + tx + SHIFT; if (x >= IMG) x -= IMG;
        grows[tid] = b * (IMG * IMG) + y * IMG + x;
    }
    __syncthreads();

    // ---- load phase: q/k rows (RoPE) + v rows, all 4 warps ----
    for (int r = warp; r < 3 * L; r += 4) {
        int kind = r / L;            // 0=q, 1=k, 2=v
        int row  = r - kind * L;
        size_t base = (size_t)grows[row] * (3 * DIM) + h * HD + (size_t)kind * DIM;
        float t1 = qkv[base + lane];
        float t2 = qkv[base + lane + 32];
        if (kind == 2) {
            Vs[row * 64 + lane]      = t1;
            Vs[row * 64 + lane + 32] = t2;
        } else {
            float s = g_sin[row * 32 + lane];
            float c = g_cos[row * 32 + lane];
            float r1 = t1 * c - t2 * s;
            float r2 = t1 * s + t2 * c;
            float* dst = (kind == 0) ? Qs : Ks;
            dst[row * 68 + lane]      = r1;
            dst[row * 68 + lane + 32] = r2;
        }
    }
    __syncthreads();

    // ---- norms (threads 0..48 -> k, 64..112 -> q) ----
    if (tid < L) {
        float ssq = 0.0f;
#pragma unroll
        for (int d4 = 0; d4 < 16; ++d4) {
            float4 v = *(const float4*)&Ks[tid * 68 + d4 * 4];
            ssq += v.x * v.x + v.y * v.y + v.z * v.z + v.w * v.w;
        }
        kn[tid] = 1.0f / fmaxf(sqrtf(ssq), 1e-12f);
    } else if (tid >= 64 && tid < 64 + L) {
        int i = tid - 64;
        float ssq = 0.0f;
#pragma unroll
        for (int d4 = 0; d4 < 16; ++d4) {
            float4 v = *(const float4*)&Qs[i * 68 + d4 * 4];
            ssq += v.x * v.x + v.y * v.y + v.z * v.z + v.w * v.w;
        }
        qn[i] = 100.0f / fmaxf(sqrtf(ssq), 1e-12f);   // 1/tau folded in
    }
    __syncthreads();

    // ---- scores: 98 threads, 2 per row (j split 0..24 / 25..48) ----
    if (tid < 2 * L) {
        int g = (tid >= L) ? 1 : 0;
        int i = tid - g * L;
        float4 qv[16];
#pragma unroll
        for (int d4 = 0; d4 < 16; ++d4)
            qv[d4] = *(const float4*)&Qs[i * 68 + d4 * 4];
        float qs = qn[i];
        int j0 = g ? 25 : 0, j1 = g ? L : 25;
        for (int j = j0; j < j1; ++j) {
            float d0 = 0.f, d1 = 0.f, d2 = 0.f, d3 = 0.f;
#pragma unroll
            for (int d4 = 0; d4 < 16; ++d4) {
                float4 k4 = *(const float4*)&Ks[j * 68 + d4 * 4];
                d0 += qv[d4].x * k4.x; d1 += qv[d4].y * k4.y;
                d2 += qv[d4].z * k4.z; d3 += qv[d4].w * k4.w;
            }
            S[i * 52 + j] = (d0 + d1 + d2 + d3) * (qs * kn[j]);
        }
    }
    __syncthreads();

    // ---- softmax per row (49 threads) ----
    if (tid < L) {
        float mx = -1e30f;
        for (int j = 0; j < L; ++j) mx = fmaxf(mx, S[tid * 52 + j]);
        float sum = 0.0f;
        for (int j = 0; j < L; ++j) {
            float e = __expf(S[tid * 52 + j] - mx);
            S[tid * 52 + j] = e;
            sum += e;
        }
        float inv = 1.0f / sum;
        for (int j = 0; j < L; ++j) S[tid * 52 + j] *= inv;
    }
    __syncthreads();

    // ---- AV: 98 threads, 2 per row (d split 0..31 / 32..63) ----
    if (tid < 2 * L) {
        int g = (tid >= L) ? 1 : 0;
        int i = tid - g * L;
        float ov[32];
#pragma unroll
        for (int d = 0; d < 32; ++d) ov[d] = 0.0f;
        for (int j = 0; j < L; ++j) {
            float wgt = S[i * 52 + j];
#pragma unroll
            for (int d4 = 0; d4 < 8; ++d4) {
                float4 v = *(const float4*)&Vs[j * 64 + g * 32 + d4 * 4];
                ov[d4 * 4 + 0] += wgt * v.x;
                ov[d4 * 4 + 1] += wgt * v.y;
                ov[d4 * 4 + 2] += wgt * v.z;
                ov[d4 * 4 + 3] += wgt * v.w;
            }
        }
#pragma unroll
        for (int d = 0; d < 32; ++d) Qs[i * 68 + g * 32 + d] = ov[d];
    }
    __syncthreads();

    // ---- scatter store as bf16 hi/lo ----
    for (int t = warp; t < L; t += 4) {
        size_t o = (size_t)grows[t] * DIM + h * HD;
        float v0 = Qs[t * 68 + lane];
        float v1 = Qs[t * 68 + lane + 32];
        uint16_t h0, l0, h1, l1;
        split1(v0, h0, l0);
        split1(v1, h1, l1);
        atthi[o + lane]      = h0;
        attlo[o + lane]      = l0;
        atthi[o + lane + 32] = h1;
        attlo[o + lane + 32] = l1;
    }
}

// ---------------------------------------------------------------------------
extern "C" void kernel_launch(void* const* d_in, const int* in_sizes, int n_in,
                              void* d_out, int out_size)
{
    const float* x     = (const float*)d_in[0];
    const float* qkv_w = (const float*)d_in[1];
    const float* projw = (const float*)d_in[2];
    float* out = (float*)d_out;

    float *qkv_ptr;
    uint16_t *xhi, *xlo, *qwhi, *qwlo, *pwhi, *pwlo, *atthi, *attlo;
    cudaGetSymbolAddress((void**)&qkv_ptr, g_qkv);
    cudaGetSymbolAddress((void**)&xhi,  g_xhi);
    cudaGetSymbolAddress((void**)&xlo,  g_xlo);
    cudaGetSymbolAddress((void**)&qwhi, g_qwhi);
    cudaGetSymbolAddress((void**)&qwlo, g_qwlo);
    cudaGetSymbolAddress((void**)&pwhi, g_pwhi);
    cudaGetSymbolAddress((void**)&pwlo, g_pwlo);
    cudaGetSymbolAddress((void**)&atthi, g_atthi);
    cudaGetSymbolAddress((void**)&attlo, g_attlo);

    cudaFuncSetAttribute(gemm_presplit_kernel,
                         cudaFuncAttributeMaxDynamicSharedMemorySize, SMEM_GEMM);

    rope_init_kernel<<<1, 256>>>();

    // pre-split inputs to bf16 hi/lo
    split_kernel<<<1024, 256>>>(x,     xhi,  xlo,  (size_t)TOKENS * DIM / 4);
    split_kernel<<<64,   256>>>(qkv_w, qwhi, qwlo, (size_t)3 * DIM * DIM / 4);
    split_kernel<<<32,   256>>>(projw, pwhi, pwlo, (size_t)DIM * DIM / 4);

    // qkv = x @ qkv_w^T : M=100352, N=2304, K=768
    gemm_presplit_kernel<<<dim3(3 * DIM / BN, TOKENS / BM), 256, SMEM_GEMM>>>(
        xhi, xlo, qwhi, qwlo, qkv_ptr, TOKENS, 3 * DIM, DIM);

    // windowed attention (writes bf16 hi/lo att)
    window_attn_kernel<<<dim3(NH, NWIN), 128>>>(qkv_ptr, atthi, attlo);

    // out = att @ proj_w^T : M=100352, N=768, K=768
    gemm_presplit_kernel<<<dim3(DIM / BN, TOKENS / BM), 256, SMEM_GEMM>>>(
        atthi, attlo, pwhi, pwlo, out, TOKENS, DIM, DIM);
}